// round 12
// baseline (speedup 1.0000x reference)
#include <cuda_runtime.h>
#include <cuda_bf16.h>

// ---------------------------------------------------------------------------
// AliasFreeActivation: bias -> up2x(12x12 FIR, pad10, gain4) -> lrelu*sqrt2,
// clamp(+-256) -> 12x12 FIR down2x.
// Input [8,128,128,128] f32 -> mid [264,264] -> out [8,128,127,127] f32.
//
// Block = 48x64 output tile, 512 threads, 2 blocks/SM (32 warps).
// Filters in __constant__ (uniform port). Input stored twice (sA, sB=shift-1)
// so overlapping pairs are direct LDS.64. Phase B computes an (even,odd)
// mid-row PAIR per job (7 shared input rows loaded once), in two jj-chunks to
// cap register liveness under the 64-reg budget. Mid parity-split into
// even/odd half-arrays (conflict-free stride-73). Phase C: 8 balanced row
// groups x 6 rows, compile-time trip counts. All FMAs are fma.rn.f32x2.
// ---------------------------------------------------------------------------

#define H      128
#define W      128
#define OHW    127
#define TY     48
#define TX     64
#define MSTR2  73          // half-mid row stride in (E,O) u64 pairs (9 mod 16)
#define INH    59          // TY+11
#define INW    78          // even => 8B-aligned u64 rows; u64 stride 39%16==7
#define QROWS  53          // mid row pairs (mid rows 0..105)
#define NTHREADS 512

#define S_SA_OFF    0
#define S_SB_OFF    (INH*INW)                    // 4602 floats
#define S_MIDE_OFF  (2*INH*INW)                  // 9204 (byte 36816, 16B)
#define S_MIDO_OFF  (S_MIDE_OFF + QROWS*MSTR2*2) // 9204+7738 = 16942 (8B)
#define SMEM_FLOATS (S_MIDO_OFF + QROWS*MSTR2*2) // 24680 -> 98720 B

typedef unsigned long long u64;

__constant__ __align__(16) float c_fu[144];
__constant__ __align__(16) float c_fd[144];

__device__ __forceinline__ u64 ffma2(u64 a, u64 b, u64 c) {
    u64 d;
    asm("fma.rn.f32x2 %0, %1, %2, %3;" : "=l"(d) : "l"(a), "l"(b), "l"(c));
    return d;
}
__device__ __forceinline__ float2 unpack2(u64 d) {
    float2 f;
    asm("mov.b64 {%0, %1}, %2;" : "=f"(f.x), "=f"(f.y) : "l"(d));
    return f;
}

// Phase C worker: 6 output rows, 22 mid rows, compile-time everything.
__device__ __forceinline__ void phase_c_group(const u64* __restrict__ hb,
                                              const u64* __restrict__ ob,
                                              u64* __restrict__ acc)
{
    #pragma unroll
    for (int r = 0; r < 6; r++) acc[r] = 0ull;

    #pragma unroll
    for (int mm = 0; mm < 22; mm++) {
        const u64* mrow = ((mm & 1) ? ob : hb) + (mm >> 1) * MSTR2;
        u64 md[6];
        #pragma unroll
        for (int s = 0; s < 6; s++) md[s] = mrow[s];

        const int rlo = (mm >= 12) ? ((mm - 10) >> 1) : 0;
        const int rhi = (mm >> 1) < 5 ? (mm >> 1) : 5;
        #pragma unroll
        for (int r = 0; r < 6; r++) {
            if (r < rlo || r > rhi) continue;       // folds at compile time
            const int ky = mm - 2 * r;              // compile-time constant
            const ulonglong2* fq = (const ulonglong2*)(c_fd + ky * 12);
            ulonglong2 f01 = fq[0], f23 = fq[1], f45 = fq[2];
            acc[r] = ffma2(md[0], f01.x, acc[r]);
            acc[r] = ffma2(md[1], f01.y, acc[r]);
            acc[r] = ffma2(md[2], f23.x, acc[r]);
            acc[r] = ffma2(md[3], f23.y, acc[r]);
            acc[r] = ffma2(md[4], f45.x, acc[r]);
            acc[r] = ffma2(md[5], f45.y, acc[r]);
        }
    }
}

__global__ __launch_bounds__(NTHREADS, 2)
void afa_fused_kernel(const float* __restrict__ in,
                      const float* __restrict__ bias,
                      float* __restrict__ out)
{
    extern __shared__ float sm[];
    float* s_sa   = sm + S_SA_OFF;
    float* s_sb   = sm + S_SB_OFF;
    u64*   s_midE = (u64*)(sm + S_MIDE_OFF);   // even mid rows, (E,O) pairs
    u64*   s_midO = (u64*)(sm + S_MIDO_OFF);   // odd  mid rows

    const int tid   = threadIdx.x;
    const int b     = blockIdx.x;
    const int plane = b / 6;                   // n*128 + c
    const int t6    = b - plane * 6;
    const int oy0   = (t6 >> 1) * TY;          // 0,48,96
    const int ox0   = (t6 & 1) * TX;
    const int iy0   = oy0 - 5;
    const int ix0   = ox0 - 5;

    const float bv = __ldg(&bias[plane & 127]);
    const float* __restrict__ inp = in + (size_t)plane * (H * W);

    // ---- Phase A: dual input copies (+bias, zero pad OOB) ------------------
    for (int i = tid; i < INH * INW; i += NTHREADS) {
        const int r  = i / INW;
        const int cc = i - r * INW;
        const int gy = iy0 + r;
        const int gx = ix0 + cc;
        float v = 0.0f;
        if ((unsigned)gy < (unsigned)H && (unsigned)gx < (unsigned)W)
            v = __ldg(&inp[gy * W + gx]) + bv;
        s_sa[i] = v;                       // sA[w] = x[w]
        if (cc > 0) s_sb[i - 1] = v;       // sB[w] = x[w+1]
    }
    __syncthreads();

    // ---- Phase B: row-PAIR polyphase up-conv + activation ------------------
    // Job tid<477: mid rows (2q, 2q+1), 16 columns (8 E/O pairs).
    // Two jj-chunks cap operand liveness (<=9 u64 live) for the 64-reg budget.
    // Gain 4 folded into activation gain G.
    const float G = 5.65685424949238019f;   // 4*sqrt(2)
    if (tid < QROWS * 9) {
        const int chunk = tid / QROWS;          // 0..8
        const int q     = tid - chunk * QROWS;  // 0..52
        const int j0    = chunk * 8;            // word base (even)

        u64 ae[8], ao[8];
        #pragma unroll
        for (int jj = 0; jj < 8; jj++) { ae[jj] = 0ull; ao[jj] = 0ull; }

        #pragma unroll
        for (int t = 0; t < 7; t++) {
            const int rowoff = (q + t) * INW + j0;
            const u64* pa = (const u64*)(s_sa + rowoff);  // (x[a],x[a+1]), a even
            const u64* pb = (const u64*)(s_sb + rowoff);  // (x[a],x[a+1]), a odd

            u64 fe0=0, fe1=0, fe2=0, fe3=0, fe4=0, fe5=0;
            u64 fo0=0, fo1=0, fo2=0, fo3=0, fo4=0, fo5=0;
            if (t < 6) {
                const ulonglong2* fq = (const ulonglong2*)(c_fu + (2 * t) * 12);
                ulonglong2 a0 = fq[0], a1 = fq[1], a2 = fq[2];
                fe0 = a0.x; fe1 = a0.y; fe2 = a1.x;
                fe3 = a1.y; fe4 = a2.x; fe5 = a2.y;
            }
            if (t >= 1) {
                const ulonglong2* fq = (const ulonglong2*)(c_fu + (2 * t - 1) * 12);
                ulonglong2 a0 = fq[0], a1 = fq[1], a2 = fq[2];
                fo0 = a0.x; fo1 = a0.y; fo2 = a1.x;
                fo3 = a1.y; fo4 = a2.x; fo5 = a2.y;
            }

            u64 pe[7], po[6];
            // chunk 1: jj = 0..3, offsets 0..8 -> pe[0..4], po[0..3]
            #pragma unroll
            for (int m = 0; m < 5; m++) pe[m] = pa[m];
            #pragma unroll
            for (int m = 0; m < 4; m++) po[m] = pb[m];
            #define PR(a) (((a) & 1) ? po[(a) >> 1] : pe[(a) >> 1])
            #pragma unroll
            for (int jj = 0; jj < 4; jj++) {
                if (t < 6) {
                    ae[jj] = ffma2(PR(jj + 0), fe0, ae[jj]);
                    ae[jj] = ffma2(PR(jj + 1), fe1, ae[jj]);
                    ae[jj] = ffma2(PR(jj + 2), fe2, ae[jj]);
                    ae[jj] = ffma2(PR(jj + 3), fe3, ae[jj]);
                    ae[jj] = ffma2(PR(jj + 4), fe4, ae[jj]);
                    ae[jj] = ffma2(PR(jj + 5), fe5, ae[jj]);
                }
                if (t >= 1) {
                    ao[jj] = ffma2(PR(jj + 0), fo0, ao[jj]);
                    ao[jj] = ffma2(PR(jj + 1), fo1, ao[jj]);
                    ao[jj] = ffma2(PR(jj + 2), fo2, ao[jj]);
                    ao[jj] = ffma2(PR(jj + 3), fo3, ao[jj]);
                    ao[jj] = ffma2(PR(jj + 4), fo4, ao[jj]);
                    ao[jj] = ffma2(PR(jj + 5), fo5, ao[jj]);
                }
            }
            // chunk 2: jj = 4..7, offsets 4..12 -> pe[2..6], po[2..5]
            pe[5] = pa[5]; pe[6] = pa[6];
            po[4] = pb[4]; po[5] = pb[5];
            #pragma unroll
            for (int jj = 4; jj < 8; jj++) {
                if (t < 6) {
                    ae[jj] = ffma2(PR(jj + 0), fe0, ae[jj]);
                    ae[jj] = ffma2(PR(jj + 1), fe1, ae[jj]);
                    ae[jj] = ffma2(PR(jj + 2), fe2, ae[jj]);
                    ae[jj] = ffma2(PR(jj + 3), fe3, ae[jj]);
                    ae[jj] = ffma2(PR(jj + 4), fe4, ae[jj]);
                    ae[jj] = ffma2(PR(jj + 5), fe5, ae[jj]);
                }
                if (t >= 1) {
                    ao[jj] = ffma2(PR(jj + 0), fo0, ao[jj]);
                    ao[jj] = ffma2(PR(jj + 1), fo1, ao[jj]);
                    ao[jj] = ffma2(PR(jj + 2), fo2, ao[jj]);
                    ao[jj] = ffma2(PR(jj + 3), fo3, ao[jj]);
                    ao[jj] = ffma2(PR(jj + 4), fo4, ao[jj]);
                    ao[jj] = ffma2(PR(jj + 5), fo5, ao[jj]);
                }
            }
            #undef PR
        }
        // activation (gain folded) + store pairs; stride 73 u64 (9 mod 16)
        u64* re = s_midE + q * MSTR2 + j0;
        u64* ro = s_midO + q * MSTR2 + j0;
        #pragma unroll
        for (int jj = 0; jj < 8; jj++) {
            float2 v = unpack2(ae[jj]);
            v.x = fminf(fmaxf(fmaxf(v.x, 0.2f * v.x) * G, -256.0f), 256.0f);
            v.y = fminf(fmaxf(fmaxf(v.y, 0.2f * v.y) * G, -256.0f), 256.0f);
            ((float2*)re)[jj] = v;
            float2 w = unpack2(ao[jj]);
            w.x = fminf(fmaxf(fmaxf(w.x, 0.2f * w.x) * G, -256.0f), 256.0f);
            w.y = fminf(fmaxf(fmaxf(w.y, 0.2f * w.y) * G, -256.0f), 256.0f);
            ((float2*)ro)[jj] = w;
        }
    }
    __syncthreads();

    // ---- Phase C: 12x12 down-conv stride 2, packed over (E,O) --------------
    // 16 warps = 8 row groups (6 rows each) x 2 col halves. lane = column.
    {
        const int wrp  = tid >> 5;
        const int lane = tid & 31;
        const int rg   = wrp >> 1;                  // 0..7
        const int c    = ((wrp & 1) << 5) + lane;   // 0..63
        const int r0   = 6 * rg;
        const u64* hb  = s_midE + r0 * MSTR2 + c;
        const u64* ob  = s_midO + r0 * MSTR2 + c;

        u64 acc[6];
        phase_c_group(hb, ob, acc);

        const int gx = ox0 + c;
        if (gx < OHW) {
            float* op = out + (size_t)plane * (OHW * OHW) + gx;
            #pragma unroll
            for (int r = 0; r < 6; r++) {
                const int gy = oy0 + r0 + r;
                if (gy < OHW) {
                    float2 v = unpack2(acc[r]);
                    op[gy * OHW] = v.x + v.y;
                }
            }
        }
    }
}

extern "C" void kernel_launch(void* const* d_in, const int* in_sizes, int n_in,
                              void* d_out, int out_size)
{
    const float* in   = (const float*)d_in[0];
    const float* bias = (const float*)d_in[1];
    const float* fu   = (const float*)d_in[2];
    const float* fd   = (const float*)d_in[3];
    float* out        = (float*)d_out;

    // Filters into constant memory (async D2D copies: graph-capturable).
    cudaMemcpyToSymbolAsync(c_fu, fu, 144 * sizeof(float), 0,
                            cudaMemcpyDeviceToDevice, 0);
    cudaMemcpyToSymbolAsync(c_fd, fd, 144 * sizeof(float), 0,
                            cudaMemcpyDeviceToDevice, 0);

    const size_t smem = SMEM_FLOATS * sizeof(float);   // 98720 B
    cudaFuncSetAttribute(afa_fused_kernel,
                         cudaFuncAttributeMaxDynamicSharedMemorySize, (int)smem);

    const int nblocks = 1024 * 6;   // planes * (3 y-tiles * 2 x-tiles)
    afa_fused_kernel<<<nblocks, NTHREADS, smem>>>(in, bias, out);
}

// round 13
// speedup vs baseline: 1.0995x; 1.0995x over previous
#include <cuda_runtime.h>
#include <cuda_bf16.h>

// ---------------------------------------------------------------------------
// AliasFreeActivation: bias -> up2x(12x12 FIR, pad10, gain4) -> lrelu*sqrt2,
// clamp(+-256) -> 12x12 FIR down2x.
// Input [8,128,128,128] f32 -> mid [264,264] -> out [8,128,127,127] f32.
//
// Block = 32x64 output tile, 384 threads. Filters in __constant__ (uniform
// port). Input stored twice (sA, sB=shift-1) so overlapping pairs are direct
// LDS.64. Phase B computes an (even,odd) mid-row PAIR per job: the 7 shared
// input rows are loaded once and feed both rows. Mid parity-split into
// even/odd half-arrays (conflict-free stride-73 stores). Phase C: balanced
// row groups {6,6,5,5,5,5} with compile-time trip counts (templated) so
// ptxas software-pipelines the mid loads. All FMAs are packed fma.rn.f32x2.
// ---------------------------------------------------------------------------

#define H      128
#define W      128
#define OHW    127
#define TY     32
#define TX     64
#define MSTR2  73          // half-mid row stride in (E,O) float2 pairs
#define INH    43
#define INW    78          // even => 8B-aligned u64 rows; u64 stride 39%16==7
#define NTHREADS 384

#define S_SA_OFF    0
#define S_SB_OFF    (INH*INW)                   // 3354
#define S_MIDE_OFF  (2*INH*INW)                 // 6708  (byte 26832, 16B)
#define S_MIDO_OFF  (S_MIDE_OFF + 37*MSTR2*2)   // 6708+5402 = 12110
#define SMEM_FLOATS (S_MIDO_OFF + 37*MSTR2*2)   // 17512 -> 70048 B

typedef unsigned long long u64;

__constant__ __align__(16) float c_fu[144];
__constant__ __align__(16) float c_fd[144];

__device__ __forceinline__ u64 ffma2(u64 a, u64 b, u64 c) {
    u64 d;
    asm("fma.rn.f32x2 %0, %1, %2, %3;" : "=l"(d) : "l"(a), "l"(b), "l"(c));
    return d;
}
__device__ __forceinline__ float2 unpack2(u64 d) {
    float2 f;
    asm("mov.b64 {%0, %1}, %2;" : "=f"(f.x), "=f"(f.y) : "l"(d));
    return f;
}

// Phase C worker: NR output rows, NM = 2*NR+10 mid rows. Compile-time trip
// counts -> full unroll, static rlo/rhi/ky folding, pipelinable loads.
template <int NR, int NM>
__device__ __forceinline__ void phase_c_group(const u64* __restrict__ hb,
                                              const u64* __restrict__ ob,
                                              u64* __restrict__ acc)
{
    #pragma unroll
    for (int r = 0; r < NR; r++) acc[r] = 0ull;

    #pragma unroll
    for (int mm = 0; mm < NM; mm++) {
        const u64* mrow = ((mm & 1) ? ob : hb) + (mm >> 1) * MSTR2;
        u64 md[6];
        #pragma unroll
        for (int s = 0; s < 6; s++) md[s] = mrow[s];

        const int rlo = (mm >= 12) ? ((mm - 10) >> 1) : 0;
        const int rhi = (mm >> 1) < (NR - 1) ? (mm >> 1) : (NR - 1);
        #pragma unroll
        for (int r = 0; r < NR; r++) {
            if (r < rlo || r > rhi) continue;       // folds at compile time
            const int ky = mm - 2 * r;              // compile-time constant
            const ulonglong2* fq = (const ulonglong2*)(c_fd + ky * 12);
            ulonglong2 f01 = fq[0], f23 = fq[1], f45 = fq[2];
            acc[r] = ffma2(md[0], f01.x, acc[r]);
            acc[r] = ffma2(md[1], f01.y, acc[r]);
            acc[r] = ffma2(md[2], f23.x, acc[r]);
            acc[r] = ffma2(md[3], f23.y, acc[r]);
            acc[r] = ffma2(md[4], f45.x, acc[r]);
            acc[r] = ffma2(md[5], f45.y, acc[r]);
        }
    }
}

__global__ __launch_bounds__(NTHREADS, 2)
void afa_fused_kernel(const float* __restrict__ in,
                      const float* __restrict__ bias,
                      float* __restrict__ out)
{
    extern __shared__ float sm[];
    float* s_sa   = sm + S_SA_OFF;
    float* s_sb   = sm + S_SB_OFF;
    u64*   s_midE = (u64*)(sm + S_MIDE_OFF);   // even mid rows, (E,O) pairs
    u64*   s_midO = (u64*)(sm + S_MIDO_OFF);   // odd  mid rows

    const int tid   = threadIdx.x;
    const int b     = blockIdx.x;
    const int plane = b >> 3;
    const int t8    = b & 7;
    const int oy0   = (t8 >> 1) * TY;
    const int ox0   = (t8 & 1) * TX;
    const int iy0   = oy0 - 5;
    const int ix0   = ox0 - 5;

    const float bv = __ldg(&bias[plane & 127]);
    const float* __restrict__ inp = in + (size_t)plane * (H * W);

    // ---- Phase A: dual input copies (+bias, zero pad OOB) ------------------
    for (int i = tid; i < INH * INW; i += NTHREADS) {
        const int r  = i / INW;
        const int cc = i - r * INW;
        const int gy = iy0 + r;
        const int gx = ix0 + cc;
        float v = 0.0f;
        if ((unsigned)gy < (unsigned)H && (unsigned)gx < (unsigned)W)
            v = __ldg(&inp[gy * W + gx]) + bv;
        s_sa[i] = v;                       // sA[w] = x[w]
        if (cc > 0) s_sb[i - 1] = v;       // sB[w] = x[w+1]
    }
    __syncthreads();

    // ---- Phase B: row-PAIR polyphase up-conv + activation ------------------
    // Job tid<333: mid rows (2q, 2q+1), 16 columns (8 E/O pairs).
    // Shared input rows q..q+6 loaded once; even row uses fu row 2t (t<6),
    // odd row uses fu row 2t-1 (t>=1). Filter offsets are compile-time.
    // Gain 4 folded into activation gain G.
    const float G = 5.65685424949238019f;   // 4*sqrt(2)
    if (tid < 333) {
        const int chunk = tid / 37;           // 0..8
        const int q     = tid - chunk * 37;   // 0..36
        const int j0    = chunk * 8;          // pair/word column base (even)

        u64 ae[8], ao[8];
        #pragma unroll
        for (int jj = 0; jj < 8; jj++) { ae[jj] = 0ull; ao[jj] = 0ull; }

        #pragma unroll
        for (int t = 0; t < 7; t++) {
            const int rowoff = (q + t) * INW + j0;         // even offset
            const u64* pa = (const u64*)(s_sa + rowoff);   // (x[a],x[a+1]), a even
            const u64* pb = (const u64*)(s_sb + rowoff);   // (x[a],x[a+1]), a odd
            u64 pe[7], po[6];
            #pragma unroll
            for (int m = 0; m < 7; m++) pe[m] = pa[m];
            #pragma unroll
            for (int m = 0; m < 6; m++) po[m] = pb[m];

            #define PR(a) (((a) & 1) ? po[(a) >> 1] : pe[(a) >> 1])
            if (t < 6) {   // even mid row, filter row 2t (compile-time)
                const ulonglong2* fq = (const ulonglong2*)(c_fu + (2 * t) * 12);
                ulonglong2 f01 = fq[0], f23 = fq[1], f45 = fq[2];
                #pragma unroll
                for (int jj = 0; jj < 8; jj++) {
                    ae[jj] = ffma2(PR(jj + 0), f01.x, ae[jj]);
                    ae[jj] = ffma2(PR(jj + 1), f01.y, ae[jj]);
                    ae[jj] = ffma2(PR(jj + 2), f23.x, ae[jj]);
                    ae[jj] = ffma2(PR(jj + 3), f23.y, ae[jj]);
                    ae[jj] = ffma2(PR(jj + 4), f45.x, ae[jj]);
                    ae[jj] = ffma2(PR(jj + 5), f45.y, ae[jj]);
                }
            }
            if (t >= 1) {  // odd mid row, filter row 2t-1 (compile-time)
                const ulonglong2* fq = (const ulonglong2*)(c_fu + (2 * t - 1) * 12);
                ulonglong2 f01 = fq[0], f23 = fq[1], f45 = fq[2];
                #pragma unroll
                for (int jj = 0; jj < 8; jj++) {
                    ao[jj] = ffma2(PR(jj + 0), f01.x, ao[jj]);
                    ao[jj] = ffma2(PR(jj + 1), f01.y, ao[jj]);
                    ao[jj] = ffma2(PR(jj + 2), f23.x, ao[jj]);
                    ao[jj] = ffma2(PR(jj + 3), f23.y, ao[jj]);
                    ao[jj] = ffma2(PR(jj + 4), f45.x, ao[jj]);
                    ao[jj] = ffma2(PR(jj + 5), f45.y, ao[jj]);
                }
            }
            #undef PR
        }
        // activation (gain folded) + store pairs; stride 73 u64 (9 mod 16)
        u64* re = s_midE + q * MSTR2 + j0;
        u64* ro = s_midO + q * MSTR2 + j0;
        #pragma unroll
        for (int jj = 0; jj < 8; jj++) {
            float2 v = unpack2(ae[jj]);
            v.x = fminf(fmaxf(fmaxf(v.x, 0.2f * v.x) * G, -256.0f), 256.0f);
            v.y = fminf(fmaxf(fmaxf(v.y, 0.2f * v.y) * G, -256.0f), 256.0f);
            ((float2*)re)[jj] = v;
            float2 w = unpack2(ao[jj]);
            w.x = fminf(fmaxf(fmaxf(w.x, 0.2f * w.x) * G, -256.0f), 256.0f);
            w.y = fminf(fmaxf(fmaxf(w.y, 0.2f * w.y) * G, -256.0f), 256.0f);
            ((float2*)ro)[jj] = w;
        }
    }
    __syncthreads();

    // ---- Phase C: 12x12 down-conv stride 2, packed over (E,O) --------------
    // 12 warps = 6 balanced row groups {6,6,5,5,5,5} x 2 col halves.
    // lane = column. Compile-time trip counts (no dynamic breaks).
    {
        const int wrp  = tid >> 5;
        const int lane = tid & 31;
        const int rg   = wrp >> 1;                  // 0..5
        const int c    = ((wrp & 1) << 5) + lane;   // 0..63
        const int r0   = (rg < 2) ? 6 * rg : 12 + 5 * (rg - 2);
        const u64* hb  = s_midE + r0 * MSTR2 + c;
        const u64* ob  = s_midO + r0 * MSTR2 + c;

        const int gx = ox0 + c;
        float* op = out + (size_t)plane * (OHW * OHW) + gx;

        if (rg < 2) {
            u64 acc[6];
            phase_c_group<6, 22>(hb, ob, acc);
            if (gx < OHW) {
                #pragma unroll
                for (int r = 0; r < 6; r++) {
                    const int gy = oy0 + r0 + r;
                    if (gy < OHW) {
                        float2 v = unpack2(acc[r]);
                        op[gy * OHW] = v.x + v.y;
                    }
                }
            }
        } else {
            u64 acc[5];
            phase_c_group<5, 20>(hb, ob, acc);
            if (gx < OHW) {
                #pragma unroll
                for (int r = 0; r < 5; r++) {
                    const int gy = oy0 + r0 + r;
                    if (gy < OHW) {
                        float2 v = unpack2(acc[r]);
                        op[gy * OHW] = v.x + v.y;
                    }
                }
            }
        }
    }
}

extern "C" void kernel_launch(void* const* d_in, const int* in_sizes, int n_in,
                              void* d_out, int out_size)
{
    const float* in   = (const float*)d_in[0];
    const float* bias = (const float*)d_in[1];
    const float* fu   = (const float*)d_in[2];
    const float* fd   = (const float*)d_in[3];
    float* out        = (float*)d_out;

    // Filters into constant memory (async D2D copies: graph-capturable).
    cudaMemcpyToSymbolAsync(c_fu, fu, 144 * sizeof(float), 0,
                            cudaMemcpyDeviceToDevice, 0);
    cudaMemcpyToSymbolAsync(c_fd, fd, 144 * sizeof(float), 0,
                            cudaMemcpyDeviceToDevice, 0);

    const size_t smem = SMEM_FLOATS * sizeof(float);   // 70048 B
    cudaFuncSetAttribute(afa_fused_kernel,
                         cudaFuncAttributeMaxDynamicSharedMemorySize, (int)smem);

    const int nblocks = 1024 * 8;
    afa_fused_kernel<<<nblocks, NTHREADS, smem>>>(in, bias, out);
}